// round 6
// baseline (speedup 1.0000x reference)
#include <cuda_runtime.h>
#include <cuda_bf16.h>

// SMorph layer: y = softdilate(x,k1) + softerode(x,k2) + bias
// Factorized via exp(p+k)=exp(p)exp(k):
//   den = conv((e,em),(A1,A2))  num = conv((pe,pem),(A1,A2)) + conv((e,em),(B1,B2))
//   out = num.x/den.x + num.y/den.y + bias   [f32x2 lanes: dilate|erode]
//
// Round 6: occupancy doubling. 63x7 tile, grid 288 (single wave), but
// 512-thread blocks = 8 chunks x 64 lanes, 1 filter per chunk per pass
// (2 passes) -> 31 resident warps/SM instead of 16. Register budget for
// 2x512 threads/SM is 64; the kernel is built to fit:
//   acc den[7]+num[7] = 28 regs, 3 hoisted kh-weights = 12, streaming
//   row register (no p[9] array) = 4.

#define BATCH 8
#define CIN   3
#define HIN   128
#define WIN   128
#define FOUT  16
#define HOUT  126
#define WOUT  126

#define TW    63           // tile width  (cols)
#define TH    7            // tile height (rows)
#define TINW  65           // TW + 2 halo
#define TINH  9            // TH + 2 halo
#define NTHREADS 512

__device__ __forceinline__ void ffma2(unsigned long long& d,
                                      unsigned long long a,
                                      unsigned long long b)
{
    asm("fma.rn.f32x2 %0, %1, %2, %0;" : "+l"(d) : "l"(a), "l"(b));
}

__device__ __forceinline__ float2 unpack2(unsigned long long v)
{
    float2 r;
    asm("mov.b64 {%0, %1}, %2;" : "=f"(r.x), "=f"(r.y) : "l"(v));
    return r;
}

__global__ __launch_bounds__(NTHREADS, 2)
void smorph_kernel(const float* __restrict__ x,
                   const float* __restrict__ k1,
                   const float* __restrict__ k2,
                   const float* __restrict__ bias,
                   float* __restrict__ out)
{
    __shared__ float4 sMap[CIN][TINH][TINW];   // (e,em,pe,pem) 3*9*65*16 = 28080 B
    __shared__ float4 sW[27][FOUT];            // (A1,A2,B1,B2)          6912 B
    __shared__ float  sBias[FOUT];

    const int tid  = threadIdx.x;
    const int fc   = tid >> 6;                 // filter chunk 0..7
    const int col  = tid & 63;                 // 0..63 (63 = idle lane)
    const int colc = min(col, TW - 1);         // keep idle lane's loads in-range
    const int bx   = blockIdx.x, by = blockIdx.y, b = blockIdx.z;
    const int gx0  = bx * TW,  gy0 = by * TH;

    // ---- Weight precompute: j = c*9 + kh*3 + kw ; mem idx ((kh*3+kw)*3+c)*16+f
    if (tid < FOUT) sBias[tid] = bias[tid];
    for (int i = tid; i < 27 * FOUT; i += NTHREADS) {
        int j = i >> 4, f = i & 15;
        int c = j / 9, r = j - c * 9;
        int gi = (r * 3 + c) * FOUT + f;
        float w1 = k1[gi], w2 = k2[gi];
        float a1 = __expf(w1), a2 = __expf(w2);
        sW[j][f] = make_float4(a1, a2, w1 * a1, w2 * a2);
    }

    // ---- Tile load + map precompute (always in-bounds: gy0+8<=127, gx0+64<=127)
    for (int i = tid; i < CIN * TINH * TINW; i += NTHREADS) {
        int c   = i / (TINH * TINW);
        int rem = i - c * (TINH * TINW);
        int r   = rem / TINW;
        int cc  = rem - r * TINW;
        float v  = x[((b * CIN + c) * HIN + (gy0 + r)) * WIN + (gx0 + cc)];
        float e  = __expf(v);
        float em = __expf(-v);
        sMap[c][r][cc] = make_float4(e, em, v * e, -v * em);
    }
    __syncthreads();

    const int ow = gx0 + col;

    // ---- Two sequential passes, ONE filter each (acc = 28 regs).
#pragma unroll 1
    for (int pass = 0; pass < 2; pass++) {
        const int f = pass * 8 + fc;           // this pass's filter

        unsigned long long den[TH], num[TH];
#pragma unroll
        for (int p = 0; p < TH; p++) { den[p] = 0ull; num[p] = 0ull; }

#pragma unroll 1
        for (int c = 0; c < CIN; c++) {
#pragma unroll
            for (int kw = 0; kw < 3; kw++) {
                // Hoist this filter's 3 kh-weights for (c,kw).
                ulonglong2 w0 = *reinterpret_cast<const ulonglong2*>(
                                    &sW[c * 9 + 0 * 3 + kw][f]);
                ulonglong2 w1 = *reinterpret_cast<const ulonglong2*>(
                                    &sW[c * 9 + 1 * 3 + kw][f]);
                ulonglong2 w2 = *reinterpret_cast<const ulonglong2*>(
                                    &sW[c * 9 + 2 * 3 + kw][f]);

                // Stream the 9 rows; row rr feeds px = rr-kh (kh=0,1,2).
#pragma unroll
                for (int rr = 0; rr < TINH; rr++) {
                    const ulonglong2 p =
                        *reinterpret_cast<const ulonglong2*>(
                            &sMap[c][rr][colc + kw]);
                    // kh = 0 -> px = rr
                    if (rr <= TH - 1) {
                        ffma2(den[rr],     p.x, w0.x);
                        ffma2(num[rr],     p.y, w0.x);
                        ffma2(num[rr],     p.x, w0.y);
                    }
                    // kh = 1 -> px = rr-1
                    if (rr >= 1 && rr <= TH) {
                        ffma2(den[rr - 1], p.x, w1.x);
                        ffma2(num[rr - 1], p.y, w1.x);
                        ffma2(num[rr - 1], p.x, w1.y);
                    }
                    // kh = 2 -> px = rr-2
                    if (rr >= 2) {
                        ffma2(den[rr - 2], p.x, w2.x);
                        ffma2(num[rr - 2], p.y, w2.x);
                        ffma2(num[rr - 2], p.x, w2.y);
                    }
                }
            }
        }

        // ---- Epilogue for this pass: 1 filter x 7 pixels
        if (col < TW) {
            const float bz = sBias[f];
#pragma unroll
            for (int px = 0; px < TH; px++) {
                float2 n = unpack2(num[px]);
                float2 d = unpack2(den[px]);
                out[((b * FOUT + f) * HOUT + (gy0 + px)) * WOUT + ow] =
                    __fdividef(n.x, d.x) + __fdividef(n.y, d.y) + bz;
            }
        }
    }
}

extern "C" void kernel_launch(void* const* d_in, const int* in_sizes, int n_in,
                              void* d_out, int out_size)
{
    const float* x    = (const float*)d_in[0];
    const float* k1   = (const float*)d_in[1];
    const float* k2   = (const float*)d_in[2];
    const float* bias = (const float*)d_in[3];
    float* out = (float*)d_out;

    dim3 grid(WOUT / TW,    // 2
              HOUT / TH,    // 18
              BATCH);       // 8
    smorph_kernel<<<grid, NTHREADS>>>(x, k1, k2, bias, out);
}